// round 8
// baseline (speedup 1.0000x reference)
#include <cuda_runtime.h>
#include <cuda_fp16.h>
#include <cstdint>
#include <math.h>

#define NN_ 64
#define PP_ 1024
#define EE_ 512
#define HH_ 8
#define MBIG (NN_*PP_)   // 65536

// dynamic smem: 3 stages x (A 8192 + B 16384 halfs) = 73728 halfs = 147456 B
#define SMEM_BYTES 147456

// ---------------- scratch (__device__ globals; no allocs allowed) ----------
// Packed-A (fp16), per 128-row panel: [K/16][8 rt][32 lane][8 halfs]
// Packed-B (fp16): [K/16][nb][32 lane][4 halfs]
__device__ __half g_xa [(size_t)512*65536];   // x packed-A, 512 panels        64MB
__device__ __half g_vp [(size_t)EE_*EE_];     // V packed-B  [32 k16][64 nb]   0.5MB
__device__ __half g_wp [(size_t)EE_*EE_];     // W^T packed-B                  0.5MB
__device__ __half g_ap [(size_t)64*131072];   // alpha_mat packed-A, 64 panels 16MB
__device__ __half g_wsp[(size_t)512*65536];   // ws packed-B per (n,h) slab    64MB
__device__ __half g_yp [(size_t)512*65536];   // y packed-A, 512 panels        64MB

// ---------------- helpers --------------------------------------------------
__device__ __forceinline__ uint32_t smem_u32(const void* p){
    uint32_t a;
    asm("{ .reg .u64 t; cvta.to.shared.u64 t, %1; cvt.u32.u64 %0, t; }":"=r"(a):"l"(p));
    return a;
}
__device__ __forceinline__ uint32_t f2h2(float a, float b){
    __half2 h = __floats2half2_rn(a, b);
    return *(uint32_t*)&h;
}
__device__ __forceinline__ float log_cosh_f(float v){
    float ax = fabsf(v);
    return ax + log1pf(expf(-2.0f*ax)) - 0.6931471805599453f;
}
__device__ __forceinline__ void mma_f16(float c[4], uint4 a, uint2 b)
{
    asm volatile("mma.sync.aligned.m16n8k16.row.col.f32.f16.f16.f32 "
        "{%0,%1,%2,%3}, {%4,%5,%6,%7}, {%8,%9}, {%0,%1,%2,%3};"
        : "+f"(c[0]), "+f"(c[1]), "+f"(c[2]), "+f"(c[3])
        : "r"(a.x), "r"(a.y), "r"(a.z), "r"(a.w), "r"(b.x), "r"(b.y));
}

// ---------------------------------------------------------------------------
// Mainloop: acc(128 x 256) += A(128xK) * B(256xK)^T, fp16 fragment-major.
// B cols s*64..s*64+63 come from slab pointer Bs (s=0..3), per-k16 stride
// bstride halfs. Tile BK=64 (4 k16). 3-stage cp.async pipeline, one sync per
// tile. 256 thr, warps 2(M)x4(N), warp tile 64x64: 32 MMAs + 12 LDS per k16.
// ---------------------------------------------------------------------------
__device__ __forceinline__ void gemm_loop(
    const __half* __restrict__ Ap,
    const __half* __restrict__ B0, const __half* __restrict__ B1,
    const __half* __restrict__ B2, const __half* __restrict__ B3,
    size_t bstride, int kt, __half* __restrict__ sm, float acc[4][8][4])
{
    const int tid = threadIdx.x, wid = tid >> 5, lane = tid & 31;
    const int wrt = (wid >> 2) * 4;   // A rt base: 0 or 4
    const int wnb = (wid & 3) * 8;    // B nb base: 0,8,16,24

    auto load_tile = [&](int tt, int buf){
        __half* dA = sm + buf*24576;
        __half* dB = dA + 8192;
        const __half* As = Ap + (size_t)tt*8192;
        #pragma unroll
        for (int i = 0; i < 4; i++) {                 // A: 1024 x 16B chunks
            int c = tid + i*256;
            uint32_t dst = smem_u32(dA + c*8);
            asm volatile("cp.async.cg.shared.global [%0], [%1], 16;"
                         :: "r"(dst), "l"(As + c*8));
        }
        #pragma unroll
        for (int i = 0; i < 8; i++) {                 // B: 2048 x 16B chunks
            int c = tid + i*256;
            int k16s = c >> 9, r = c & 511;
            int nb = r >> 4, lp = r & 15;
            const __half* base = (nb & 16) ? ((nb & 8) ? B3 : B2)
                                           : ((nb & 8) ? B1 : B0);
            const __half* src = base + (size_t)(tt*4 + k16s)*bstride
                              + (nb & 7)*128 + lp*8;
            uint32_t dst = smem_u32(dB + k16s*4096 + nb*128 + lp*8);
            asm volatile("cp.async.cg.shared.global [%0], [%1], 16;"
                         :: "r"(dst), "l"(src));
        }
        asm volatile("cp.async.commit_group;" ::: "memory");
    };

    load_tile(0, 0);
    if (kt > 1) load_tile(1, 1);

    for (int tt = 0; tt < kt; tt++) {
        const int cur = tt % 3;
        asm volatile("cp.async.wait_group 1;" ::: "memory");
        __syncthreads();
        if (tt + 2 < kt) load_tile(tt + 2, (tt + 2) % 3);

        const uint4* fA = (const uint4*)(sm + cur*24576);
        const uint2* fB = (const uint2*)(sm + cur*24576 + 8192);
        #pragma unroll
        for (int ks = 0; ks < 4; ks++) {
            uint4 a[4]; uint2 b[8];
            #pragma unroll
            for (int tm = 0; tm < 4; tm++)
                a[tm] = fA[ks*256 + (wrt + tm)*32 + lane];
            #pragma unroll
            for (int tn = 0; tn < 8; tn++)
                b[tn] = fB[ks*1024 + (wnb + tn)*32 + lane];
            #pragma unroll
            for (int tm = 0; tm < 4; tm++)
                #pragma unroll
                for (int tn = 0; tn < 8; tn++)
                    mma_f16(acc[tm][tn], a[tm], b[tn]);
        }
    }
}

// ---------------------------------------------------------------------------
// Stage 1: ws[n,p,hr] = x @ V^T; epilogue writes packed-B fp16 slabs g_wsp.
// grid (x: 2 hr-tiles of 256, y: 512 m-tiles of 128)
// ---------------------------------------------------------------------------
__global__ __launch_bounds__(256) void k_stage1()
{
    extern __shared__ __half smh[];
    const int bn = blockIdx.x * 256;
    const int bm = blockIdx.y * 128;
    float acc[4][8][4] = {};
    const __half* b0 = g_vp + (bn >> 3) * 128;
    gemm_loop(g_xa + (size_t)(bm >> 7)*65536,
              b0, b0 + 1024, b0 + 2048, b0 + 3072, 8192, 8, smh, acc);

    __syncthreads();
    float* Ts = (float*)smh;   // Ts[hrloc 256][ploc 128], stride 132
    const int tid = threadIdx.x, wid = tid >> 5, lane = tid & 31;
    const int wm = (wid >> 2) * 64, wn = (wid & 3) * 64;
    const int gg = lane >> 2, tq = lane & 3;
    #pragma unroll
    for (int tm = 0; tm < 4; tm++)
        #pragma unroll
        for (int tn = 0; tn < 8; tn++) {
            int m0 = wm + tm*16 + gg, n0 = wn + tn*8 + 2*tq;
            Ts[(n0    )*132 + m0    ] = acc[tm][tn][0];
            Ts[(n0 + 1)*132 + m0    ] = acc[tm][tn][1];
            Ts[(n0    )*132 + m0 + 8] = acc[tm][tn][2];
            Ts[(n0 + 1)*132 + m0 + 8] = acc[tm][tn][3];
        }
    __syncthreads();

    const int n = bm >> 10, pbase = bm & 1023;
    #pragma unroll
    for (int i = 0; i < 32; i++) {
        int u = tid + i*256;
        int k16rel = u >> 10, rest = u & 1023;
        int nbg = rest >> 5, l = rest & 31;
        int g = l >> 2, t = l & 3;
        int hrloc = nbg*8 + g;
        int hrAbs = bn + hrloc;
        const float* ts = Ts + hrloc*132 + k16rel*16 + 2*t;
        uint2 v;
        v.x = f2h2(ts[0], ts[1]);
        v.y = f2h2(ts[8], ts[9]);
        size_t dst = (size_t)(n*8 + (hrAbs >> 6))*65536
                   + (size_t)((pbase >> 4) + k16rel)*1024
                   + ((hrAbs >> 3) & 7)*128 + l*4;
        *(uint2*)(g_wsp + dst) = v;
    }
}

// ---------------------------------------------------------------------------
// Stage 2: y[n,p,h*64+r] = alpha_mat @ ws; epilogue writes packed-A fp16 g_yp.
// Four n per block (B slabs). grid (x: 16 n-quads, y: h*8 + ptile)
// ---------------------------------------------------------------------------
__global__ __launch_bounds__(256) void k_stage2()
{
    extern __shared__ __half smh[];
    const int n0 = blockIdx.x * 4;
    const int h  = blockIdx.y >> 3;
    const int pt = blockIdx.y & 7;
    float acc[4][8][4] = {};
    gemm_loop(g_ap + (size_t)(h*8 + pt)*131072,
              g_wsp + (size_t)((n0    )*8 + h)*65536,
              g_wsp + (size_t)((n0 + 1)*8 + h)*65536,
              g_wsp + (size_t)((n0 + 2)*8 + h)*65536,
              g_wsp + (size_t)((n0 + 3)*8 + h)*65536,
              1024, 16, smh, acc);

    __syncthreads();
    float* S = (float*)smh;   // S[ploc 128][col 256], stride 264
    const int tid = threadIdx.x, wid = tid >> 5, lane = tid & 31;
    const int wm = (wid >> 2) * 64, wn = (wid & 3) * 64;
    const int gg = lane >> 2, tq = lane & 3;
    #pragma unroll
    for (int tm = 0; tm < 4; tm++)
        #pragma unroll
        for (int tn = 0; tn < 8; tn++) {
            int m0 = wm + tm*16 + gg, c0 = wn + tn*8 + 2*tq;
            S[(m0    )*264 + c0    ] = acc[tm][tn][0];
            S[(m0    )*264 + c0 + 1] = acc[tm][tn][1];
            S[(m0 + 8)*264 + c0    ] = acc[tm][tn][2];
            S[(m0 + 8)*264 + c0 + 1] = acc[tm][tn][3];
        }
    __syncthreads();

    #pragma unroll
    for (int i = 0; i < 16; i++) {
        int u = tid + i*256;
        int nloc = u >> 10, rest = u & 1023;
        int k16rel = rest >> 8, rt = (rest >> 5) & 7, l = rest & 31;
        int g = l >> 2, t = l & 3;
        int row0 = rt*16 + g;
        const float* s0 = S + row0*264 + nloc*64 + k16rel*16 + 2*t;
        const float* s1 = s0 + 8*264;
        uint4 v;
        v.x = f2h2(s0[0], s0[1]);
        v.y = f2h2(s1[0], s1[1]);
        v.z = f2h2(s0[8], s0[9]);
        v.w = f2h2(s1[8], s1[9]);
        size_t dst = (size_t)((n0 + nloc)*8 + pt)*65536
                   + (size_t)(h*4 + k16rel)*2048 + rt*256 + l*8;
        *(uint4*)(g_yp + dst) = v;
    }
}

// ---------------------------------------------------------------------------
// Stage 3: out[m][e] = log_cosh( y @ W + b )
// grid (x: 2 e-tiles of 256, y: 512 m-tiles of 128)
// ---------------------------------------------------------------------------
__global__ __launch_bounds__(256) void k_stage3(const float* __restrict__ bias,
                                                float* __restrict__ out)
{
    extern __shared__ __half smh[];
    const int bn = blockIdx.x * 256;
    const int bm = blockIdx.y * 128;
    float acc[4][8][4] = {};
    const __half* b0 = g_wp + (bn >> 3) * 128;
    gemm_loop(g_yp + (size_t)(bm >> 7)*65536,
              b0, b0 + 1024, b0 + 2048, b0 + 3072, 8192, 8, smh, acc);

    const int tid = threadIdx.x, wid = tid >> 5, lane = tid & 31;
    const int wm = (wid >> 2) * 64, wn = (wid & 3) * 64;
    const int gg = lane >> 2, tq = lane & 3;
    #pragma unroll
    for (int tn = 0; tn < 8; tn++) {
        int n0 = wn + tn*8 + 2*tq;
        float bb0 = bias[bn + n0], bb1 = bias[bn + n0 + 1];
        #pragma unroll
        for (int tm = 0; tm < 4; tm++) {
            int m0 = bm + wm + tm*16 + gg;
            float2 v0 = make_float2(log_cosh_f(acc[tm][tn][0] + bb0),
                                    log_cosh_f(acc[tm][tn][1] + bb1));
            float2 v1 = make_float2(log_cosh_f(acc[tm][tn][2] + bb0),
                                    log_cosh_f(acc[tm][tn][3] + bb1));
            *(float2*)(out + (size_t)(m0    )*EE_ + bn + n0) = v0;
            *(float2*)(out + (size_t)(m0 + 8)*EE_ + bn + n0) = v1;
        }
    }
}

// ---------------------------------------------------------------------------
// Prep: pack operands into fp16 fragment-major layouts
// ---------------------------------------------------------------------------
__global__ void k_pack_x(const float* __restrict__ x)   // grid (512 panels, 8 kslabs)
{
    __shared__ float S[128*68];
    const int panel = blockIdx.x, kslab = blockIdx.y;   // kslab covers 64 cols (4 k16)
    const int tid = threadIdx.x;
    #pragma unroll
    for (int i = 0; i < 8; i++) {
        int c = tid + i*256;               // 2048 x 16B chunks
        int row = c >> 4, seg = c & 15;
        float4 v = *(const float4*)(x + (size_t)(panel*128 + row)*512 + kslab*64 + seg*4);
        *(float4*)(S + row*68 + seg*4) = v;
    }
    __syncthreads();
    #pragma unroll
    for (int i = 0; i < 4; i++) {
        int u = tid + i*256;
        int k16 = u >> 8, rt = (u >> 5) & 7, l = u & 31;
        int g = l >> 2, t = l & 3;
        const float* s0 = S + (rt*16 + g)*68 + k16*16 + 2*t;
        const float* s1 = s0 + 8*68;
        uint4 v;
        v.x = f2h2(s0[0], s0[1]);
        v.y = f2h2(s1[0], s1[1]);
        v.z = f2h2(s0[8], s0[9]);
        v.w = f2h2(s1[8], s1[9]);
        *(uint4*)(g_xa + (size_t)panel*65536 + (size_t)(kslab*4 + k16)*2048
                  + rt*256 + l*8) = v;
    }
}

__global__ void k_pack_v(const float* __restrict__ V)   // grid (32 k16, 8)
{
    int k16 = blockIdx.x, nb = blockIdx.y*8 + (threadIdx.x >> 5), l = threadIdx.x & 31;
    int g = l >> 2, t = l & 3;
    const float* r = V + (size_t)(nb*8 + g)*512 + k16*16 + 2*t;
    uint2 v;
    v.x = f2h2(r[0], r[1]);
    v.y = f2h2(r[8], r[9]);
    *(uint2*)(g_vp + k16*8192 + nb*128 + l*4) = v;
}

__global__ void k_pack_w(const float* __restrict__ W)   // packs W^T; grid (32, 8)
{
    int k16 = blockIdx.x, nb = blockIdx.y*8 + (threadIdx.x >> 5), l = threadIdx.x & 31;
    int g = l >> 2, t = l & 3;
    int e = nb*8 + g, k = k16*16 + 2*t;
    uint2 v;
    v.x = f2h2(W[(size_t)(k    )*512 + e], W[(size_t)(k + 1)*512 + e]);
    v.y = f2h2(W[(size_t)(k + 8)*512 + e], W[(size_t)(k + 9)*512 + e]);
    *(uint2*)(g_wp + k16*8192 + nb*128 + l*4) = v;
}

__global__ void k_pack_amat(const float* __restrict__ alpha)  // grid (8 k16c, 8 pt, 8 h)
{
    __shared__ float as_[1024];
    const int k16c = blockIdx.x, pt = blockIdx.y, h = blockIdx.z;
    const int tid = threadIdx.x;
    for (int i = tid; i < 1024; i += 256) as_[i] = alpha[h*1024 + i];
    __syncthreads();
    #pragma unroll
    for (int i = 0; i < 8; i++) {
        int u = tid + i*256;
        int k16r = u >> 8, rt = (u >> 5) & 7, l = u & 31;
        int g = l >> 2, t = l & 3;
        int j = (k16c*8 + k16r)*16 + 2*t;
        int p = pt*128 + rt*16 + g;
        uint4 v;
        v.x = f2h2(as_[(j     - p) & 1023], as_[(j + 1 - p) & 1023]);
        v.y = f2h2(as_[(j - 8 - p) & 1023], as_[(j - 7 - p) & 1023]);
        v.z = f2h2(as_[(j + 8 - p) & 1023], as_[(j + 9 - p) & 1023]);
        v.w = f2h2(as_[(j     - p) & 1023], as_[(j + 1 - p) & 1023]);
        v.w = f2h2(as_[(j + 8 - p - 8) & 1023], as_[(j + 9 - p - 8) & 1023]);
        *(uint4*)(g_ap + (size_t)(h*8 + pt)*131072
                  + (size_t)(k16c*8 + k16r)*2048 + rt*256 + l*8) = v;
    }
}

// ---------------------------------------------------------------------------
extern "C" void kernel_launch(void* const* d_in, const int* in_sizes, int n_in,
                              void* d_out, int out_size)
{
    const float* x     = (const float*)d_in[0];
    const float* alpha = (const float*)d_in[1];
    const float* V     = (const float*)d_in[2];
    const float* W     = (const float*)d_in[3];
    const float* b     = (const float*)d_in[4];
    float* out = (float*)d_out;

    cudaFuncSetAttribute(k_stage1, cudaFuncAttributeMaxDynamicSharedMemorySize, SMEM_BYTES);
    cudaFuncSetAttribute(k_stage2, cudaFuncAttributeMaxDynamicSharedMemorySize, SMEM_BYTES);
    cudaFuncSetAttribute(k_stage3, cudaFuncAttributeMaxDynamicSharedMemorySize, SMEM_BYTES);

    // Prep: pack all operands to fragment-major fp16 layouts
    k_pack_x   <<<dim3(512, 8), 256>>>(x);
    k_pack_v   <<<dim3(32, 8),  256>>>(V);
    k_pack_w   <<<dim3(32, 8),  256>>>(W);
    k_pack_amat<<<dim3(8, 8, 8), 256>>>(alpha);

    // Stage 1: ws = (x @ V^T), packed-B out     M=65536 N=512 K=512
    k_stage1<<<dim3(2, 512), 256, SMEM_BYTES>>>();
    // Stage 2: y = alpha_mat @ ws, packed-A out M=1024 N=256 K=1024 (x64 batches)
    k_stage2<<<dim3(16, 64), 256, SMEM_BYTES>>>();
    // Stage 3: out = log_cosh(y @ W + b)        M=65536 N=512 K=512
    k_stage3<<<dim3(2, 512), 256, SMEM_BYTES>>>(b, out);
}

// round 9
// speedup vs baseline: 1.0642x; 1.0642x over previous
#include <cuda_runtime.h>
#include <cuda_fp16.h>
#include <cstdint>
#include <math.h>

#define NN_ 64
#define PP_ 1024
#define EE_ 512
#define HH_ 8
#define MBIG (NN_*PP_)   // 65536

// dynamic smem: 4 stages x (A 8192 + B 16384 halfs) = 98304 halfs = 196608 B
#define SMEM_BYTES 196608

// ---------------- scratch (__device__ globals; no allocs allowed) ----------
// Packed-A (fp16), per 128-row panel: [K/16][8 rt][32 lane][8 halfs]
// Packed-B (fp16): [K/16][nb][32 lane][4 halfs]
__device__ __half g_xa [(size_t)512*65536];   // x packed-A, 512 panels        64MB
__device__ __half g_vp [(size_t)EE_*EE_];     // V packed-B  [32 k16][64 nb]   0.5MB
__device__ __half g_wp [(size_t)EE_*EE_];     // W^T packed-B                  0.5MB
__device__ __half g_ap [(size_t)64*131072];   // alpha_mat packed-A, 64 panels 16MB
__device__ __half g_wsp[(size_t)512*65536];   // ws packed-B per (n,h) slab    64MB
__device__ __half g_yp [(size_t)512*65536];   // y packed-A, 512 panels        64MB

// ---------------- helpers --------------------------------------------------
__device__ __forceinline__ uint32_t smem_u32(const void* p){
    uint32_t a;
    asm("{ .reg .u64 t; cvta.to.shared.u64 t, %1; cvt.u32.u64 %0, t; }":"=r"(a):"l"(p));
    return a;
}
__device__ __forceinline__ uint32_t f2h2(float a, float b){
    __half2 h = __floats2half2_rn(a, b);
    return *(uint32_t*)&h;
}
__device__ __forceinline__ float log_cosh_f(float v){
    float ax = fabsf(v);
    return ax + log1pf(expf(-2.0f*ax)) - 0.6931471805599453f;
}
__device__ __forceinline__ void mma_f16(float c[4], uint4 a, uint2 b)
{
    asm volatile("mma.sync.aligned.m16n8k16.row.col.f32.f16.f16.f32 "
        "{%0,%1,%2,%3}, {%4,%5,%6,%7}, {%8,%9}, {%0,%1,%2,%3};"
        : "+f"(c[0]), "+f"(c[1]), "+f"(c[2]), "+f"(c[3])
        : "r"(a.x), "r"(a.y), "r"(a.z), "r"(a.w), "r"(b.x), "r"(b.y));
}

// ---------------------------------------------------------------------------
// Mainloop: acc(128 x 256) += A(128xK) * B(256xK)^T, fp16 fragment-major.
// 512 threads, warps 2(M)x8(N), warp tile 64x32 (acc 64 regs/thread).
// B cols s*64.. from slab Bs (s=0..3), per-k16 stride bstride halfs.
// Tile BK=64 (4 k16). 4-stage cp.async pipeline, wait_group 2, 1 sync/tile.
// ---------------------------------------------------------------------------
__device__ __forceinline__ void gemm_loop(
    const __half* __restrict__ Ap,
    const __half* __restrict__ B0, const __half* __restrict__ B1,
    const __half* __restrict__ B2, const __half* __restrict__ B3,
    size_t bstride, int kt, __half* __restrict__ sm, float acc[4][4][4])
{
    const int tid = threadIdx.x, wid = tid >> 5, lane = tid & 31;
    const int wrt = (wid >> 3) * 4;   // A rt base: 0 or 4
    const int wnb = (wid & 7) * 4;    // B nb base: 0,4,...,28

    auto load_tile = [&](int tt, int buf){
        __half* dA = sm + buf*24576;
        __half* dB = dA + 8192;
        const __half* As = Ap + (size_t)tt*8192;
        #pragma unroll
        for (int i = 0; i < 2; i++) {                 // A: 1024 x 16B chunks
            int c = tid + i*512;
            uint32_t dst = smem_u32(dA + c*8);
            asm volatile("cp.async.cg.shared.global [%0], [%1], 16;"
                         :: "r"(dst), "l"(As + c*8));
        }
        #pragma unroll
        for (int i = 0; i < 4; i++) {                 // B: 2048 x 16B chunks
            int c = tid + i*512;
            int k16s = c >> 9, r = c & 511;
            int nb = r >> 4, lp = r & 15;
            const __half* base = (nb & 16) ? ((nb & 8) ? B3 : B2)
                                           : ((nb & 8) ? B1 : B0);
            const __half* src = base + (size_t)(tt*4 + k16s)*bstride
                              + (nb & 7)*128 + lp*8;
            uint32_t dst = smem_u32(dB + k16s*4096 + nb*128 + lp*8);
            asm volatile("cp.async.cg.shared.global [%0], [%1], 16;"
                         :: "r"(dst), "l"(src));
        }
        asm volatile("cp.async.commit_group;" ::: "memory");
    };

    load_tile(0, 0);
    if (kt > 1) load_tile(1, 1);
    if (kt > 2) load_tile(2, 2);

    for (int tt = 0; tt < kt; tt++) {
        const int cur = tt & 3;
        if (tt + 1 < kt) {
            asm volatile("cp.async.wait_group 2;" ::: "memory");
        } else {
            asm volatile("cp.async.wait_group 0;" ::: "memory");
        }
        __syncthreads();
        if (tt + 3 < kt) load_tile(tt + 3, (tt + 3) & 3);

        const uint4* fA = (const uint4*)(sm + cur*24576);
        const uint2* fB = (const uint2*)(sm + cur*24576 + 8192);
        #pragma unroll
        for (int ks = 0; ks < 4; ks++) {
            uint4 a[4]; uint2 b[4];
            #pragma unroll
            for (int tm = 0; tm < 4; tm++)
                a[tm] = fA[ks*256 + (wrt + tm)*32 + lane];
            #pragma unroll
            for (int tn = 0; tn < 4; tn++)
                b[tn] = fB[ks*1024 + (wnb + tn)*32 + lane];
            #pragma unroll
            for (int tm = 0; tm < 4; tm++)
                #pragma unroll
                for (int tn = 0; tn < 4; tn++)
                    mma_f16(acc[tm][tn], a[tm], b[tn]);
        }
    }
}

// ---------------------------------------------------------------------------
// Stage 1: ws[n,p,hr] = x @ V^T; epilogue writes packed-B fp16 slabs g_wsp.
// grid (x: 2 hr-tiles of 256, y: 512 m-tiles of 128)
// ---------------------------------------------------------------------------
__global__ __launch_bounds__(512) void k_stage1()
{
    extern __shared__ __half smh[];
    const int bn = blockIdx.x * 256;
    const int bm = blockIdx.y * 128;
    float acc[4][4][4] = {};
    const __half* b0 = g_vp + (bn >> 3) * 128;
    gemm_loop(g_xa + (size_t)(bm >> 7)*65536,
              b0, b0 + 1024, b0 + 2048, b0 + 3072, 8192, 8, smh, acc);

    __syncthreads();
    float* Ts = (float*)smh;   // Ts[hrloc 256][ploc 128], stride 132 = 135168 B
    const int tid = threadIdx.x, wid = tid >> 5, lane = tid & 31;
    const int wm = (wid >> 3) * 64, wn = (wid & 7) * 32;
    const int gg = lane >> 2, tq = lane & 3;
    #pragma unroll
    for (int tm = 0; tm < 4; tm++)
        #pragma unroll
        for (int tn = 0; tn < 4; tn++) {
            int m0 = wm + tm*16 + gg, n0 = wn + tn*8 + 2*tq;
            Ts[(n0    )*132 + m0    ] = acc[tm][tn][0];
            Ts[(n0 + 1)*132 + m0    ] = acc[tm][tn][1];
            Ts[(n0    )*132 + m0 + 8] = acc[tm][tn][2];
            Ts[(n0 + 1)*132 + m0 + 8] = acc[tm][tn][3];
        }
    __syncthreads();

    const int n = bm >> 10, pbase = bm & 1023;
    #pragma unroll
    for (int i = 0; i < 16; i++) {
        int u = tid + i*512;
        int k16rel = u >> 10, rest = u & 1023;
        int nbg = rest >> 5, l = rest & 31;
        int g = l >> 2, t = l & 3;
        int hrloc = nbg*8 + g;
        int hrAbs = bn + hrloc;
        const float* ts = Ts + hrloc*132 + k16rel*16 + 2*t;
        uint2 v;
        v.x = f2h2(ts[0], ts[1]);
        v.y = f2h2(ts[8], ts[9]);
        size_t dst = (size_t)(n*8 + (hrAbs >> 6))*65536
                   + (size_t)((pbase >> 4) + k16rel)*1024
                   + ((hrAbs >> 3) & 7)*128 + l*4;
        *(uint2*)(g_wsp + dst) = v;
    }
}

// ---------------------------------------------------------------------------
// Stage 2: y[n,p,h*64+r] = alpha_mat @ ws; epilogue writes packed-A fp16 g_yp.
// Four n per block (B slabs). grid (x: 16 n-quads, y: h*8 + ptile)
// ---------------------------------------------------------------------------
__global__ __launch_bounds__(512) void k_stage2()
{
    extern __shared__ __half smh[];
    const int n0 = blockIdx.x * 4;
    const int h  = blockIdx.y >> 3;
    const int pt = blockIdx.y & 7;
    float acc[4][4][4] = {};
    gemm_loop(g_ap + (size_t)(h*8 + pt)*131072,
              g_wsp + (size_t)((n0    )*8 + h)*65536,
              g_wsp + (size_t)((n0 + 1)*8 + h)*65536,
              g_wsp + (size_t)((n0 + 2)*8 + h)*65536,
              g_wsp + (size_t)((n0 + 3)*8 + h)*65536,
              1024, 16, smh, acc);

    __syncthreads();
    float* S = (float*)smh;   // S[ploc 128][col 256], stride 264 = 135168 B
    const int tid = threadIdx.x, wid = tid >> 5, lane = tid & 31;
    const int wm = (wid >> 3) * 64, wn = (wid & 7) * 32;
    const int gg = lane >> 2, tq = lane & 3;
    #pragma unroll
    for (int tm = 0; tm < 4; tm++)
        #pragma unroll
        for (int tn = 0; tn < 4; tn++) {
            int m0 = wm + tm*16 + gg, c0 = wn + tn*8 + 2*tq;
            S[(m0    )*264 + c0    ] = acc[tm][tn][0];
            S[(m0    )*264 + c0 + 1] = acc[tm][tn][1];
            S[(m0 + 8)*264 + c0    ] = acc[tm][tn][2];
            S[(m0 + 8)*264 + c0 + 1] = acc[tm][tn][3];
        }
    __syncthreads();

    #pragma unroll
    for (int i = 0; i < 8; i++) {
        int u = tid + i*512;
        int nloc = u >> 10, rest = u & 1023;
        int k16rel = rest >> 8, rt = (rest >> 5) & 7, l = rest & 31;
        int g = l >> 2, t = l & 3;
        int row0 = rt*16 + g;
        const float* s0 = S + row0*264 + nloc*64 + k16rel*16 + 2*t;
        const float* s1 = s0 + 8*264;
        uint4 v;
        v.x = f2h2(s0[0], s0[1]);
        v.y = f2h2(s1[0], s1[1]);
        v.z = f2h2(s0[8], s0[9]);
        v.w = f2h2(s1[8], s1[9]);
        size_t dst = (size_t)((n0 + nloc)*8 + pt)*65536
                   + (size_t)(h*4 + k16rel)*2048 + rt*256 + l*8;
        *(uint4*)(g_yp + dst) = v;
    }
}

// ---------------------------------------------------------------------------
// Stage 3: out[m][e] = log_cosh( y @ W + b )
// grid (x: 2 e-tiles of 256, y: 512 m-tiles of 128)
// ---------------------------------------------------------------------------
__global__ __launch_bounds__(512) void k_stage3(const float* __restrict__ bias,
                                                float* __restrict__ out)
{
    extern __shared__ __half smh[];
    const int bn = blockIdx.x * 256;
    const int bm = blockIdx.y * 128;
    float acc[4][4][4] = {};
    const __half* b0 = g_wp + (bn >> 3) * 128;
    gemm_loop(g_yp + (size_t)(bm >> 7)*65536,
              b0, b0 + 1024, b0 + 2048, b0 + 3072, 8192, 8, smh, acc);

    const int tid = threadIdx.x, wid = tid >> 5, lane = tid & 31;
    const int wm = (wid >> 3) * 64, wn = (wid & 7) * 32;
    const int gg = lane >> 2, tq = lane & 3;
    #pragma unroll
    for (int tn = 0; tn < 4; tn++) {
        int n0 = wn + tn*8 + 2*tq;
        float bb0 = bias[bn + n0], bb1 = bias[bn + n0 + 1];
        #pragma unroll
        for (int tm = 0; tm < 4; tm++) {
            int m0 = bm + wm + tm*16 + gg;
            float2 v0 = make_float2(log_cosh_f(acc[tm][tn][0] + bb0),
                                    log_cosh_f(acc[tm][tn][1] + bb1));
            float2 v1 = make_float2(log_cosh_f(acc[tm][tn][2] + bb0),
                                    log_cosh_f(acc[tm][tn][3] + bb1));
            *(float2*)(out + (size_t)(m0    )*EE_ + bn + n0) = v0;
            *(float2*)(out + (size_t)(m0 + 8)*EE_ + bn + n0) = v1;
        }
    }
}

// ---------------------------------------------------------------------------
// Prep: pack operands into fp16 fragment-major layouts
// ---------------------------------------------------------------------------
__global__ void k_pack_x(const float* __restrict__ x)   // grid (512 panels, 8 kslabs)
{
    __shared__ float S[128*68];
    const int panel = blockIdx.x, kslab = blockIdx.y;   // kslab covers 64 cols (4 k16)
    const int tid = threadIdx.x;
    #pragma unroll
    for (int i = 0; i < 8; i++) {
        int c = tid + i*256;               // 2048 x 16B chunks
        int row = c >> 4, seg = c & 15;
        float4 v = *(const float4*)(x + (size_t)(panel*128 + row)*512 + kslab*64 + seg*4);
        *(float4*)(S + row*68 + seg*4) = v;
    }
    __syncthreads();
    #pragma unroll
    for (int i = 0; i < 4; i++) {
        int u = tid + i*256;
        int k16 = u >> 8, rt = (u >> 5) & 7, l = u & 31;
        int g = l >> 2, t = l & 3;
        const float* s0 = S + (rt*16 + g)*68 + k16*16 + 2*t;
        const float* s1 = s0 + 8*68;
        uint4 v;
        v.x = f2h2(s0[0], s0[1]);
        v.y = f2h2(s1[0], s1[1]);
        v.z = f2h2(s0[8], s0[9]);
        v.w = f2h2(s1[8], s1[9]);
        *(uint4*)(g_xa + (size_t)panel*65536 + (size_t)(kslab*4 + k16)*2048
                  + rt*256 + l*8) = v;
    }
}

__global__ void k_pack_v(const float* __restrict__ V)   // grid (32 k16, 8)
{
    int k16 = blockIdx.x, nb = blockIdx.y*8 + (threadIdx.x >> 5), l = threadIdx.x & 31;
    int g = l >> 2, t = l & 3;
    const float* r = V + (size_t)(nb*8 + g)*512 + k16*16 + 2*t;
    uint2 v;
    v.x = f2h2(r[0], r[1]);
    v.y = f2h2(r[8], r[9]);
    *(uint2*)(g_vp + k16*8192 + nb*128 + l*4) = v;
}

__global__ void k_pack_w(const float* __restrict__ W)   // packs W^T; grid (32, 8)
{
    int k16 = blockIdx.x, nb = blockIdx.y*8 + (threadIdx.x >> 5), l = threadIdx.x & 31;
    int g = l >> 2, t = l & 3;
    int e = nb*8 + g, k = k16*16 + 2*t;
    uint2 v;
    v.x = f2h2(W[(size_t)(k    )*512 + e], W[(size_t)(k + 1)*512 + e]);
    v.y = f2h2(W[(size_t)(k + 8)*512 + e], W[(size_t)(k + 9)*512 + e]);
    *(uint2*)(g_wp + k16*8192 + nb*128 + l*4) = v;
}

__global__ void k_pack_amat(const float* __restrict__ alpha)  // grid (8 k16c, 8 pt, 8 h)
{
    __shared__ float as_[1024];
    const int k16c = blockIdx.x, pt = blockIdx.y, h = blockIdx.z;
    const int tid = threadIdx.x;
    for (int i = tid; i < 1024; i += 256) as_[i] = alpha[h*1024 + i];
    __syncthreads();
    #pragma unroll
    for (int i = 0; i < 8; i++) {
        int u = tid + i*256;
        int k16r = u >> 8, rt = (u >> 5) & 7, l = u & 31;
        int g = l >> 2, t = l & 3;
        int j = (k16c*8 + k16r)*16 + 2*t;
        int p = pt*128 + rt*16 + g;
        uint4 v;
        v.x = f2h2(as_[(j     - p) & 1023], as_[(j + 1 - p) & 1023]);
        v.y = f2h2(as_[(j - 8 - p) & 1023], as_[(j - 7 - p) & 1023]);
        v.z = f2h2(as_[(j + 8 - p) & 1023], as_[(j + 9 - p) & 1023]);
        v.w = f2h2(as_[(j     - p) & 1023], as_[(j + 1 - p) & 1023]);
        v.w = f2h2(as_[(j + 8 - p - 8) & 1023], as_[(j + 9 - p - 8) & 1023]);
        *(uint4*)(g_ap + (size_t)(h*8 + pt)*131072
                  + (size_t)(k16c*8 + k16r)*2048 + rt*256 + l*8) = v;
    }
}

// ---------------------------------------------------------------------------
extern "C" void kernel_launch(void* const* d_in, const int* in_sizes, int n_in,
                              void* d_out, int out_size)
{
    const float* x     = (const float*)d_in[0];
    const float* alpha = (const float*)d_in[1];
    const float* V     = (const float*)d_in[2];
    const float* W     = (const float*)d_in[3];
    const float* b     = (const float*)d_in[4];
    float* out = (float*)d_out;

    cudaFuncSetAttribute(k_stage1, cudaFuncAttributeMaxDynamicSharedMemorySize, SMEM_BYTES);
    cudaFuncSetAttribute(k_stage2, cudaFuncAttributeMaxDynamicSharedMemorySize, SMEM_BYTES);
    cudaFuncSetAttribute(k_stage3, cudaFuncAttributeMaxDynamicSharedMemorySize, SMEM_BYTES);

    // Prep: pack all operands to fragment-major fp16 layouts
    k_pack_x   <<<dim3(512, 8), 256>>>(x);
    k_pack_v   <<<dim3(32, 8),  256>>>(V);
    k_pack_w   <<<dim3(32, 8),  256>>>(W);
    k_pack_amat<<<dim3(8, 8, 8), 256>>>(alpha);

    // Stage 1: ws = (x @ V^T), packed-B out     M=65536 N=512 K=512
    k_stage1<<<dim3(2, 512), 512, SMEM_BYTES>>>();
    // Stage 2: y = alpha_mat @ ws, packed-A out M=1024 N=256 K=1024 (x64 batches)
    k_stage2<<<dim3(16, 64), 512, SMEM_BYTES>>>();
    // Stage 3: out = log_cosh(y @ W + b)        M=65536 N=512 K=512
    k_stage3<<<dim3(2, 512), 512, SMEM_BYTES>>>(b, out);
}

// round 10
// speedup vs baseline: 1.1035x; 1.0370x over previous
#include <cuda_runtime.h>
#include <cuda_fp16.h>
#include <cstdint>
#include <math.h>

#define NN_ 64
#define PP_ 1024
#define EE_ 512
#define HH_ 8
#define MBIG (NN_*PP_)   // 65536

// dynamic smem: 3 stages x (A 8192 + B 8192 halfs) = 49152 halfs = 98304 B
#define SMEM_BYTES 98304

// ---------------- scratch (__device__ globals; no allocs allowed) ----------
// Packed-A (fp16), per 128-row panel: [K/16][8 rt][32 lane][8 halfs]
//   lane(g=l>>2,t=l&3): {A[rt*16+g][16k+2t],[+1], A[+8 row][2t],[+1], A[g][2t+8],[+9], A[g+8][2t+8],[+9]}
// Packed-B (fp16): [K/16][nb][32 lane][4 halfs]: {B[nb*8+g][16k+2t],[+1],[2t+8],[+9]}
__device__ __half g_xa [(size_t)512*65536];   // x packed-A, 512 panels        64MB
__device__ __half g_vp [(size_t)EE_*EE_];     // V packed-B  [32 k16][64 nb]   0.5MB
__device__ __half g_wp [(size_t)EE_*EE_];     // W^T packed-B                  0.5MB
__device__ __half g_ap [(size_t)64*131072];   // alpha_mat packed-A, 64 panels 16MB
__device__ __half g_wsp[(size_t)512*65536];   // ws packed-B per (n,h) slab    64MB
__device__ __half g_yp [(size_t)512*65536];   // y packed-A, 512 panels        64MB

// ---------------- helpers --------------------------------------------------
__device__ __forceinline__ uint32_t smem_u32(const void* p){
    uint32_t a;
    asm("{ .reg .u64 t; cvta.to.shared.u64 t, %1; cvt.u32.u64 %0, t; }":"=r"(a):"l"(p));
    return a;
}
__device__ __forceinline__ uint32_t f2h2(float a, float b){
    __half2 h = __floats2half2_rn(a, b);
    return *(uint32_t*)&h;
}
__device__ __forceinline__ float log_cosh_f(float v){
    float ax = fabsf(v);
    return ax + log1pf(expf(-2.0f*ax)) - 0.6931471805599453f;
}
__device__ __forceinline__ void mma_f16(float c[4], uint4 a, uint2 b)
{
    asm volatile("mma.sync.aligned.m16n8k16.row.col.f32.f16.f16.f32 "
        "{%0,%1,%2,%3}, {%4,%5,%6,%7}, {%8,%9}, {%0,%1,%2,%3};"
        : "+f"(c[0]), "+f"(c[1]), "+f"(c[2]), "+f"(c[3])
        : "r"(a.x), "r"(a.y), "r"(a.z), "r"(a.w), "r"(b.x), "r"(b.y));
}

// ---------------------------------------------------------------------------
// Mainloop: acc(128x128) += A(128xK) * B(128xK)^T, fp16 fragment-major packed.
// Tile BK=64 (4 k16 steps). 3-stage cp.async pipeline, one sync per tile.
// 256 thr, warps 2(M)x4(N), warp tile 64x32. 64 MMAs + 32 LDS per warp-tile.
// A slab/tile: 8192 halfs contiguous at Ap + tt*8192.
// B per k16: nb 0..7 from B0, 8..15 from B1; per-k16 stride bstride (halfs).
// ---------------------------------------------------------------------------
__device__ __forceinline__ void gemm_loop(
    const __half* __restrict__ Ap,
    const __half* __restrict__ B0, const __half* __restrict__ B1,
    size_t bstride, int kt, __half* __restrict__ sm, float acc[4][4][4])
{
    const int tid = threadIdx.x, wid = tid >> 5, lane = tid & 31;
    const int wrt = (wid >> 2) * 4;   // A rt base: 0 or 4
    const int wnb = (wid & 3) * 4;    // B nb base: 0,4,8,12

    auto load_tile = [&](int tt, int buf){
        __half* dA = sm + buf*16384;
        __half* dB = dA + 8192;
        const __half* As = Ap + (size_t)tt*8192;
        #pragma unroll
        for (int i = 0; i < 4; i++) {                 // A: 1024 x 16B chunks
            int c = tid + i*256;
            uint32_t dst = smem_u32(dA + c*8);
            asm volatile("cp.async.cg.shared.global [%0], [%1], 16;"
                         :: "r"(dst), "l"(As + c*8));
        }
        #pragma unroll
        for (int i = 0; i < 4; i++) {                 // B: 1024 x 16B chunks
            int c = tid + i*256;
            int k16s = c >> 8, r = c & 255;
            int nb = r >> 4, lp = r & 15;
            const __half* src = ((nb & 8) ? B1 : B0)
                              + (size_t)(tt*4 + k16s)*bstride + (nb & 7)*128 + lp*8;
            uint32_t dst = smem_u32(dB + k16s*2048 + nb*128 + lp*8);
            asm volatile("cp.async.cg.shared.global [%0], [%1], 16;"
                         :: "r"(dst), "l"(src));
        }
        asm volatile("cp.async.commit_group;" ::: "memory");
    };

    load_tile(0, 0);
    if (kt > 1) load_tile(1, 1);

    for (int tt = 0; tt < kt; tt++) {
        const int cur = tt % 3;
        asm volatile("cp.async.wait_group 1;" ::: "memory");
        __syncthreads();
        if (tt + 2 < kt) load_tile(tt + 2, (tt + 2) % 3);

        const uint4* fA = (const uint4*)(sm + cur*16384);
        const uint2* fB = (const uint2*)(sm + cur*16384 + 8192);
        #pragma unroll
        for (int ks = 0; ks < 4; ks++) {
            uint4 a[4]; uint2 b[4];
            #pragma unroll
            for (int tm = 0; tm < 4; tm++)
                a[tm] = fA[ks*256 + (wrt + tm)*32 + lane];
            #pragma unroll
            for (int tn = 0; tn < 4; tn++)
                b[tn] = fB[ks*512 + (wnb + tn)*32 + lane];
            #pragma unroll
            for (int tm = 0; tm < 4; tm++)
                #pragma unroll
                for (int tn = 0; tn < 4; tn++)
                    mma_f16(acc[tm][tn], a[tm], b[tn]);
        }
    }
}

// ---------------------------------------------------------------------------
// Stage 1: ws[n,p,hr] = x @ V^T; epilogue writes packed-B fp16 slabs g_wsp.
// grid (x: 4 hr-tiles of 128, y: 512 m-tiles of 128)
// ---------------------------------------------------------------------------
__global__ __launch_bounds__(256, 2) void k_stage1()
{
    extern __shared__ __half smh[];
    const int bn = blockIdx.x * 128;
    const int bm = blockIdx.y * 128;
    float acc[4][4][4] = {};
    const __half* b0 = g_vp + (bn >> 3) * 128;
    gemm_loop(g_xa + (size_t)(bm >> 7)*65536, b0, b0 + 1024, 8192, 8, smh, acc);

    __syncthreads();
    float* Ts = (float*)smh;   // Ts[hrloc][ploc], stride 132 (transposed C)
    const int tid = threadIdx.x, wid = tid >> 5, lane = tid & 31;
    const int wm = (wid >> 2) * 64, wn = (wid & 3) * 32;
    const int gg = lane >> 2, tq = lane & 3;
    #pragma unroll
    for (int tm = 0; tm < 4; tm++)
        #pragma unroll
        for (int tn = 0; tn < 4; tn++) {
            int m0 = wm + tm*16 + gg, n0 = wn + tn*8 + 2*tq;
            Ts[(n0    )*132 + m0    ] = acc[tm][tn][0];
            Ts[(n0 + 1)*132 + m0    ] = acc[tm][tn][1];
            Ts[(n0    )*132 + m0 + 8] = acc[tm][tn][2];
            Ts[(n0 + 1)*132 + m0 + 8] = acc[tm][tn][3];
        }
    __syncthreads();

    const int n = bm >> 10, pbase = bm & 1023;
    #pragma unroll
    for (int i = 0; i < 16; i++) {
        int u = tid + i*256;
        int k16rel = u >> 9, rest = u & 511;
        int nbg = rest >> 5, l = rest & 31;
        int g = l >> 2, t = l & 3;
        int hrloc = nbg*8 + g;
        int hrAbs = bn + hrloc;
        const float* ts = Ts + hrloc*132 + k16rel*16 + 2*t;
        uint2 v;
        v.x = f2h2(ts[0], ts[1]);
        v.y = f2h2(ts[8], ts[9]);
        size_t dst = (size_t)(n*8 + (hrAbs >> 6))*65536
                   + (size_t)((pbase >> 4) + k16rel)*1024
                   + ((hrAbs >> 3) & 7)*128 + l*4;
        *(uint2*)(g_wsp + dst) = v;
    }
}

// ---------------------------------------------------------------------------
// Stage 2: y[n,p,h*64+r] = alpha_mat @ ws; epilogue writes packed-A fp16 g_yp.
// Two n per block (B halves). grid (x: 32 n-pairs, y: h*8 + ptile)
// ---------------------------------------------------------------------------
__global__ __launch_bounds__(256, 2) void k_stage2()
{
    extern __shared__ __half smh[];
    const int n0 = blockIdx.x * 2;
    const int h  = blockIdx.y >> 3;
    const int pt = blockIdx.y & 7;
    float acc[4][4][4] = {};
    gemm_loop(g_ap + (size_t)(h*8 + pt)*131072,
              g_wsp + (size_t)(n0*8 + h)*65536,
              g_wsp + (size_t)((n0+1)*8 + h)*65536,
              1024, 16, smh, acc);

    __syncthreads();
    float* S = (float*)smh;   // S[ploc][col], stride 132; col = half*64 + r
    const int tid = threadIdx.x, wid = tid >> 5, lane = tid & 31;
    const int wm = (wid >> 2) * 64, wn = (wid & 3) * 32;
    const int gg = lane >> 2, tq = lane & 3;
    #pragma unroll
    for (int tm = 0; tm < 4; tm++)
        #pragma unroll
        for (int tn = 0; tn < 4; tn++) {
            int m0 = wm + tm*16 + gg, c0 = wn + tn*8 + 2*tq;
            S[(m0    )*132 + c0    ] = acc[tm][tn][0];
            S[(m0    )*132 + c0 + 1] = acc[tm][tn][1];
            S[(m0 + 8)*132 + c0    ] = acc[tm][tn][2];
            S[(m0 + 8)*132 + c0 + 1] = acc[tm][tn][3];
        }
    __syncthreads();

    #pragma unroll
    for (int i = 0; i < 8; i++) {
        int u = tid + i*256;
        int half_ = u >> 10, v_ = u & 1023;
        int k16rel = v_ >> 8, rt = (v_ >> 5) & 7, l = v_ & 31;
        int g = l >> 2, t = l & 3;
        int row0 = rt*16 + g;
        const float* s0 = S + row0*132 + half_*64 + k16rel*16 + 2*t;
        const float* s1 = s0 + 8*132;
        uint4 v;
        v.x = f2h2(s0[0], s0[1]);
        v.y = f2h2(s1[0], s1[1]);
        v.z = f2h2(s0[8], s0[9]);
        v.w = f2h2(s1[8], s1[9]);
        size_t dst = (size_t)((n0 + half_)*8 + pt)*65536
                   + (size_t)(h*4 + k16rel)*2048 + rt*256 + l*8;
        *(uint4*)(g_yp + dst) = v;
    }
}

// ---------------------------------------------------------------------------
// Stage 3: out[m][e] = log_cosh( y @ W + b )
// grid (x: 4 e-tiles of 128, y: 512 m-tiles of 128)
// ---------------------------------------------------------------------------
__global__ __launch_bounds__(256, 2) void k_stage3(const float* __restrict__ bias,
                                                   float* __restrict__ out)
{
    extern __shared__ __half smh[];
    const int bn = blockIdx.x * 128;
    const int bm = blockIdx.y * 128;
    float acc[4][4][4] = {};
    const __half* b0 = g_wp + (bn >> 3) * 128;
    gemm_loop(g_yp + (size_t)(bm >> 7)*65536, b0, b0 + 1024, 8192, 8, smh, acc);

    const int tid = threadIdx.x, wid = tid >> 5, lane = tid & 31;
    const int wm = (wid >> 2) * 64, wn = (wid & 3) * 32;
    const int gg = lane >> 2, tq = lane & 3;
    #pragma unroll
    for (int tn = 0; tn < 4; tn++) {
        int n0 = wn + tn*8 + 2*tq;
        float bb0 = bias[bn + n0], bb1 = bias[bn + n0 + 1];
        #pragma unroll
        for (int tm = 0; tm < 4; tm++) {
            int m0 = bm + wm + tm*16 + gg;
            float2 v0 = make_float2(log_cosh_f(acc[tm][tn][0] + bb0),
                                    log_cosh_f(acc[tm][tn][1] + bb1));
            float2 v1 = make_float2(log_cosh_f(acc[tm][tn][2] + bb0),
                                    log_cosh_f(acc[tm][tn][3] + bb1));
            *(float2*)(out + (size_t)(m0    )*EE_ + bn + n0) = v0;
            *(float2*)(out + (size_t)(m0 + 8)*EE_ + bn + n0) = v1;
        }
    }
}

// ---------------------------------------------------------------------------
// Prep: pack operands into fp16 fragment-major layouts
// ---------------------------------------------------------------------------
__global__ void k_pack_x(const float* __restrict__ x)   // grid (512 panels, 8 kslabs)
{
    __shared__ float S[128*68];
    const int panel = blockIdx.x, kslab = blockIdx.y;   // kslab covers 64 cols (4 k16)
    const int tid = threadIdx.x;
    #pragma unroll
    for (int i = 0; i < 8; i++) {
        int c = tid + i*256;               // 2048 x 16B chunks
        int row = c >> 4, seg = c & 15;
        float4 v = *(const float4*)(x + (size_t)(panel*128 + row)*512 + kslab*64 + seg*4);
        *(float4*)(S + row*68 + seg*4) = v;
    }
    __syncthreads();
    #pragma unroll
    for (int i = 0; i < 4; i++) {
        int u = tid + i*256;
        int k16 = u >> 8, rt = (u >> 5) & 7, l = u & 31;
        int g = l >> 2, t = l & 3;
        const float* s0 = S + (rt*16 + g)*68 + k16*16 + 2*t;
        const float* s1 = s0 + 8*68;
        uint4 v;
        v.x = f2h2(s0[0], s0[1]);
        v.y = f2h2(s1[0], s1[1]);
        v.z = f2h2(s0[8], s0[9]);
        v.w = f2h2(s1[8], s1[9]);
        *(uint4*)(g_xa + (size_t)panel*65536 + (size_t)(kslab*4 + k16)*2048
                  + rt*256 + l*8) = v;
    }
}

__global__ void k_pack_v(const float* __restrict__ V)   // grid (32 k16, 8)
{
    int k16 = blockIdx.x, nb = blockIdx.y*8 + (threadIdx.x >> 5), l = threadIdx.x & 31;
    int g = l >> 2, t = l & 3;
    const float* r = V + (size_t)(nb*8 + g)*512 + k16*16 + 2*t;
    uint2 v;
    v.x = f2h2(r[0], r[1]);
    v.y = f2h2(r[8], r[9]);
    *(uint2*)(g_vp + k16*8192 + nb*128 + l*4) = v;
}

__global__ void k_pack_w(const float* __restrict__ W)   // packs W^T; grid (32, 8)
{
    int k16 = blockIdx.x, nb = blockIdx.y*8 + (threadIdx.x >> 5), l = threadIdx.x & 31;
    int g = l >> 2, t = l & 3;
    int e = nb*8 + g, k = k16*16 + 2*t;
    uint2 v;
    v.x = f2h2(W[(size_t)(k    )*512 + e], W[(size_t)(k + 1)*512 + e]);
    v.y = f2h2(W[(size_t)(k + 8)*512 + e], W[(size_t)(k + 9)*512 + e]);
    *(uint2*)(g_wp + k16*8192 + nb*128 + l*4) = v;
}

__global__ void k_pack_amat(const float* __restrict__ alpha)  // grid (8 k16c, 8 pt, 8 h)
{
    __shared__ float as_[1024];
    const int k16c = blockIdx.x, pt = blockIdx.y, h = blockIdx.z;
    const int tid = threadIdx.x;
    for (int i = tid; i < 1024; i += 256) as_[i] = alpha[h*1024 + i];
    __syncthreads();
    #pragma unroll
    for (int i = 0; i < 8; i++) {
        int u = tid + i*256;
        int k16r = u >> 8, rt = (u >> 5) & 7, l = u & 31;
        int g = l >> 2, t = l & 3;
        int j = (k16c*8 + k16r)*16 + 2*t;
        int p = pt*128 + rt*16 + g;
        uint4 v;
        v.x = f2h2(as_[(j     - p) & 1023], as_[(j + 1 - p) & 1023]);
        v.y = f2h2(as_[(j - 8 - p) & 1023], as_[(j - 7 - p) & 1023]);
        v.z = f2h2(as_[(j + 8 - p) & 1023], as_[(j + 9 - p) & 1023]);
        v.w = f2h2(as_[(j     - p) & 1023], as_[(j + 1 - p) & 1023]);
        *(uint4*)(g_ap + (size_t)(h*8 + pt)*131072
                  + (size_t)(k16c*8 + k16r)*2048 + rt*256 + l*8) = v;
    }
}

// ---------------------------------------------------------------------------
extern "C" void kernel_launch(void* const* d_in, const int* in_sizes, int n_in,
                              void* d_out, int out_size)
{
    const float* x     = (const float*)d_in[0];
    const float* alpha = (const float*)d_in[1];
    const float* V     = (const float*)d_in[2];
    const float* W     = (const float*)d_in[3];
    const float* b     = (const float*)d_in[4];
    float* out = (float*)d_out;

    cudaFuncSetAttribute(k_stage1, cudaFuncAttributeMaxDynamicSharedMemorySize, SMEM_BYTES);
    cudaFuncSetAttribute(k_stage2, cudaFuncAttributeMaxDynamicSharedMemorySize, SMEM_BYTES);
    cudaFuncSetAttribute(k_stage3, cudaFuncAttributeMaxDynamicSharedMemorySize, SMEM_BYTES);

    // Prep: pack all operands to fragment-major fp16 layouts
    k_pack_x   <<<dim3(512, 8), 256>>>(x);
    k_pack_v   <<<dim3(32, 8),  256>>>(V);
    k_pack_w   <<<dim3(32, 8),  256>>>(W);
    k_pack_amat<<<dim3(8, 8, 8), 256>>>(alpha);

    // Stage 1: ws = (x @ V^T), packed-B out     M=65536 N=512 K=512
    k_stage1<<<dim3(4, 512), 256, SMEM_BYTES>>>();
    // Stage 2: y = alpha_mat @ ws, packed-A out M=1024 N=128 K=1024 (x64 batches)
    k_stage2<<<dim3(32, 64), 256, SMEM_BYTES>>>();
    // Stage 3: out = log_cosh(y @ W + b)        M=65536 N=512 K=512
    k_stage3<<<dim3(4, 512), 256, SMEM_BYTES>>>(b, out);
}